// round 1
// baseline (speedup 1.0000x reference)
#include <cuda_runtime.h>
#include <cstdint>

// Problem constants
#define Bb   256
#define Tt   512
#define Ii   64
#define Hh   512
#define NCTA 128   // persistent CTAs (<= 148 SMs -> single wave, co-resident)
#define NH   4     // h columns owned per CTA (NCTA*NH == Hh)
#define NG   16    // gate columns per CTA (4 gates * NH)
#define NTHR 256   // one thread per batch element

// Persistent device state (allocations are forbidden; __device__ globals are the
// sanctioned scratch). h double buffer stored [buf][k][b] so batch is contiguous.
__device__ float    g_h[2][Hh][Bb];     // 1 MB
__device__ unsigned g_count;            // grid barrier counter (reset by init each launch)

// ---------- packed f32x2 helpers ----------
__device__ __forceinline__ unsigned long long pack2(float lo, float hi) {
    unsigned long long r;
    asm("mov.b64 %0, {%1,%2};" : "=l"(r) : "f"(lo), "f"(hi));
    return r;
}
__device__ __forceinline__ void unpack2(unsigned long long v, float& lo, float& hi) {
    asm("mov.b64 {%0,%1}, %2;" : "=f"(lo), "=f"(hi) : "l"(v));
}
__device__ __forceinline__ void fma2(unsigned long long& acc,
                                     unsigned long long a, unsigned long long b) {
    // acc = a*b + acc  (2x fp32 per lane; FFMA2 is PTX-only on Blackwell)
    asm("fma.rn.f32x2 %0, %1, %2, %0;" : "+l"(acc) : "l"(a), "l"(b));
}

// ---------- activations (accurate fast-math; tanh via exp to stay ~1e-6) ----------
__device__ __forceinline__ float sigm(float x) {
    return __fdividef(1.f, 1.f + __expf(-x));
}
__device__ __forceinline__ float tanh_(float x) {
    x = fminf(fmaxf(x, -15.f), 15.f);      // avoid inf/inf
    float e = __expf(2.f * x);
    return __fdividef(e - 1.f, e + 1.f);
}

// ---------- init: zero h0, reset barrier counter (runs every graph replay) ----------
__global__ void init_kernel() {
    int idx = blockIdx.x * blockDim.x + threadIdx.x;
    float* p = &g_h[0][0][0];
    for (int i = idx; i < Hh * Bb; i += gridDim.x * blockDim.x) p[i] = 0.f;
    if (idx == 0) g_count = 0u;
}

// ---------- persistent LSTM kernel ----------
__global__ void __launch_bounds__(NTHR, 1) lstm_kernel(
    const float* __restrict__ x,      // [B, T, I]
    const float* __restrict__ W_ih,   // [4H, I]
    const float* __restrict__ W_hh,   // [4H, H]
    const float* __restrict__ b_ih,   // [4H]
    const float* __restrict__ b_hh)   // [4H]
{
    __shared__ __align__(16) float Ws[Hh * NG];   // W_hh slice, [k][col], 32 KB
    __shared__ __align__(16) float Wx[Ii * NG];   // W_ih slice, [i][col], 4 KB
    __shared__ float bs[NG];

    const int tid = threadIdx.x;
    const int j0  = blockIdx.x * NH;

    // One-time weight staging. col = j*4 + gate, gate order (i,f,g,o) => row = gate*H + j0 + j
    for (int idx = tid; idx < Hh * NG; idx += NTHR) {
        int k = idx >> 4, col = idx & 15;
        int row = (col & 3) * Hh + j0 + (col >> 2);
        Ws[idx] = W_hh[row * Hh + k];
    }
    for (int idx = tid; idx < Ii * NG; idx += NTHR) {
        int i = idx >> 4, col = idx & 15;
        int row = (col & 3) * Hh + j0 + (col >> 2);
        Wx[idx] = W_ih[row * Ii + i];
    }
    if (tid < NG) {
        int row = (tid & 3) * Hh + j0 + (tid >> 2);
        bs[tid] = b_ih[row] + b_hh[row];
    }
    __syncthreads();

    const int b = tid;                           // one batch element per thread
    float c[NH] = {0.f, 0.f, 0.f, 0.f};

    unsigned long long bias[8];
    #pragma unroll
    for (int p = 0; p < 8; p++) bias[p] = pack2(bs[2*p], bs[2*p+1]);

    const float4* xp = reinterpret_cast<const float4*>(x) + (size_t)b * (Tt * Ii / 4);

    for (int t = 0; t < Tt; t++) {
        const float* hA = &g_h[t & 1][0][0];
        float*       hB = &g_h[(t + 1) & 1][0][0];

        unsigned long long acc[8];
        #pragma unroll
        for (int p = 0; p < 8; p++) acc[p] = bias[p];

        // ---- recurrent GEMM slice: gates[b, col] += sum_k h[k][b] * Ws[k][col]
        #pragma unroll 8
        for (int k = 0; k < Hh; k++) {
            float hk = __ldcv(hA + k * Bb + b);          // bypass L1 (written by peer SMs)
            unsigned long long h2 = pack2(hk, hk);
            const unsigned long long* w =
                reinterpret_cast<const unsigned long long*>(Ws + k * NG);
            #pragma unroll
            for (int p = 0; p < 8; p++) fma2(acc[p], h2, w[p]);
        }

        // ---- fused input projection: gates += x[b,t,:] @ Wx
        #pragma unroll
        for (int q = 0; q < Ii / 4; q++) {
            float4 xv = xp[t * (Ii / 4) + q];
            float xe[4] = {xv.x, xv.y, xv.z, xv.w};
            #pragma unroll
            for (int e = 0; e < 4; e++) {
                unsigned long long x2 = pack2(xe[e], xe[e]);
                const unsigned long long* w =
                    reinterpret_cast<const unsigned long long*>(Wx + (q * 4 + e) * NG);
                #pragma unroll
                for (int p = 0; p < 8; p++) fma2(acc[p], x2, w[p]);
            }
        }

        float a[NG];
        #pragma unroll
        for (int p = 0; p < 8; p++) unpack2(acc[p], a[2*p], a[2*p+1]);

        // ---- elementwise LSTM cell + h write (coalesced across b)
        #pragma unroll
        for (int j = 0; j < NH; j++) {
            float iv = sigm(a[j*4 + 0]);
            float fv = sigm(a[j*4 + 1]);
            float gv = tanh_(a[j*4 + 2]);
            float ov = sigm(a[j*4 + 3]);
            c[j] = fv * c[j] + iv * gv;
            hB[(j0 + j) * Bb + b] = ov * tanh_(c[j]);
        }

        // ---- grid barrier (skip after last step; kernel boundary syncs for fc)
        if (t < Tt - 1) {
            __threadfence();                 // release h writes
            __syncthreads();
            if (tid == 0) {
                atomicAdd(&g_count, 1u);
                unsigned target = (unsigned)(t + 1) * gridDim.x;
                while (*((volatile unsigned*)&g_count) < target) { /* spin */ }
            }
            __syncthreads();
            __threadfence();                 // acquire before next step's h reads
        }
    }
}

// ---------- final FC: out[b] = h_T[:,b] . W_fc + b_fc ----------
__global__ void fc_kernel(const float* __restrict__ W_fc,
                          const float* __restrict__ b_fc,
                          float* __restrict__ out) {
    int b = threadIdx.x;
    float s = 0.f;
    #pragma unroll 16
    for (int k = 0; k < Hh; k++)
        s += g_h[0][k][b] * W_fc[k];        // final h lands in buffer 0 (T even)
    out[b] = s + b_fc[0];
}

extern "C" void kernel_launch(void* const* d_in, const int* in_sizes, int n_in,
                              void* d_out, int out_size) {
    const float* x    = (const float*)d_in[0];
    const float* W_ih = (const float*)d_in[1];
    const float* W_hh = (const float*)d_in[2];
    const float* b_ih = (const float*)d_in[3];
    const float* b_hh = (const float*)d_in[4];
    const float* W_fc = (const float*)d_in[5];
    const float* b_fc = (const float*)d_in[6];
    float* out = (float*)d_out;

    init_kernel<<<128, 256>>>();
    lstm_kernel<<<NCTA, NTHR>>>(x, W_ih, W_hh, b_ih, b_hh);
    fc_kernel<<<1, Bb>>>(W_fc, b_fc, out);
}

// round 2
// speedup vs baseline: 1.0062x; 1.0062x over previous
#include <cuda_runtime.h>
#include <cstdint>

// Problem constants
#define Bb   256
#define Tt   512
#define Ii   64
#define Hh   512
#define NCTA 128   // persistent CTAs (<= 148 SMs -> single wave, co-resident)
#define NH   4     // h columns owned per CTA (NCTA*NH == Hh)
#define NG   16    // gate columns per CTA (4 gates * NH)
#define NTHR 256   // one thread per batch element

// Persistent device state (allocations are forbidden; __device__ globals are the
// sanctioned scratch). h double buffer stored [buf][k][b] so batch is contiguous.
__device__ float    g_h[2][Hh][Bb];     // 1 MB
__device__ unsigned g_count;            // grid barrier counter (reset by init each launch)

// ---------- packed f32x2 helpers ----------
__device__ __forceinline__ unsigned long long pack2(float lo, float hi) {
    unsigned long long r;
    asm("mov.b64 %0, {%1,%2};" : "=l"(r) : "f"(lo), "f"(hi));
    return r;
}
__device__ __forceinline__ void unpack2(unsigned long long v, float& lo, float& hi) {
    asm("mov.b64 {%0,%1}, %2;" : "=f"(lo), "=f"(hi) : "l"(v));
}
__device__ __forceinline__ void fma2(unsigned long long& acc,
                                     unsigned long long a, unsigned long long b) {
    // acc = a*b + acc  (2x fp32 per lane; FFMA2 is PTX-only on Blackwell)
    asm("fma.rn.f32x2 %0, %1, %2, %0;" : "+l"(acc) : "l"(a), "l"(b));
}

// ---------- activations (accurate fast-math; tanh via exp to stay ~1e-6) ----------
__device__ __forceinline__ float sigm(float x) {
    return __fdividef(1.f, 1.f + __expf(-x));
}
__device__ __forceinline__ float tanh_(float x) {
    x = fminf(fmaxf(x, -15.f), 15.f);      // avoid inf/inf
    float e = __expf(2.f * x);
    return __fdividef(e - 1.f, e + 1.f);
}

// ---------- init: zero h0, reset barrier counter (runs every graph replay) ----------
__global__ void init_kernel() {
    int idx = blockIdx.x * blockDim.x + threadIdx.x;
    float* p = &g_h[0][0][0];
    for (int i = idx; i < Hh * Bb; i += gridDim.x * blockDim.x) p[i] = 0.f;
    if (idx == 0) g_count = 0u;
}

// ---------- persistent LSTM kernel ----------
__global__ void __launch_bounds__(NTHR, 1) lstm_kernel(
    const float* __restrict__ x,      // [B, T, I]
    const float* __restrict__ W_ih,   // [4H, I]
    const float* __restrict__ W_hh,   // [4H, H]
    const float* __restrict__ b_ih,   // [4H]
    const float* __restrict__ b_hh)   // [4H]
{
    __shared__ __align__(16) float Ws[Hh * NG];   // W_hh slice, [k][col], 32 KB
    __shared__ __align__(16) float Wx[Ii * NG];   // W_ih slice, [i][col], 4 KB
    __shared__ float bs[NG];

    const int tid = threadIdx.x;
    const int j0  = blockIdx.x * NH;

    // One-time weight staging. col = j*4 + gate, gate order (i,f,g,o) => row = gate*H + j0 + j
    for (int idx = tid; idx < Hh * NG; idx += NTHR) {
        int k = idx >> 4, col = idx & 15;
        int row = (col & 3) * Hh + j0 + (col >> 2);
        Ws[idx] = W_hh[row * Hh + k];
    }
    for (int idx = tid; idx < Ii * NG; idx += NTHR) {
        int i = idx >> 4, col = idx & 15;
        int row = (col & 3) * Hh + j0 + (col >> 2);
        Wx[idx] = W_ih[row * Ii + i];
    }
    if (tid < NG) {
        int row = (tid & 3) * Hh + j0 + (tid >> 2);
        bs[tid] = b_ih[row] + b_hh[row];
    }
    __syncthreads();

    const int b = tid;                           // one batch element per thread
    float c[NH] = {0.f, 0.f, 0.f, 0.f};

    unsigned long long bias[8];
    #pragma unroll
    for (int p = 0; p < 8; p++) bias[p] = pack2(bs[2*p], bs[2*p+1]);

    const float4* xp = reinterpret_cast<const float4*>(x) + (size_t)b * (Tt * Ii / 4);

    for (int t = 0; t < Tt; t++) {
        const float* hA = &g_h[t & 1][0][0];
        float*       hB = &g_h[(t + 1) & 1][0][0];

        unsigned long long acc[8];
        #pragma unroll
        for (int p = 0; p < 8; p++) acc[p] = bias[p];

        // ---- recurrent GEMM slice: gates[b, col] += sum_k h[k][b] * Ws[k][col]
        #pragma unroll 8
        for (int k = 0; k < Hh; k++) {
            float hk = __ldcv(hA + k * Bb + b);          // bypass L1 (written by peer SMs)
            unsigned long long h2 = pack2(hk, hk);
            const unsigned long long* w =
                reinterpret_cast<const unsigned long long*>(Ws + k * NG);
            #pragma unroll
            for (int p = 0; p < 8; p++) fma2(acc[p], h2, w[p]);
        }

        // ---- fused input projection: gates += x[b,t,:] @ Wx
        #pragma unroll
        for (int q = 0; q < Ii / 4; q++) {
            float4 xv = xp[t * (Ii / 4) + q];
            float xe[4] = {xv.x, xv.y, xv.z, xv.w};
            #pragma unroll
            for (int e = 0; e < 4; e++) {
                unsigned long long x2 = pack2(xe[e], xe[e]);
                const unsigned long long* w =
                    reinterpret_cast<const unsigned long long*>(Wx + (q * 4 + e) * NG);
                #pragma unroll
                for (int p = 0; p < 8; p++) fma2(acc[p], x2, w[p]);
            }
        }

        float a[NG];
        #pragma unroll
        for (int p = 0; p < 8; p++) unpack2(acc[p], a[2*p], a[2*p+1]);

        // ---- elementwise LSTM cell + h write (coalesced across b)
        #pragma unroll
        for (int j = 0; j < NH; j++) {
            float iv = sigm(a[j*4 + 0]);
            float fv = sigm(a[j*4 + 1]);
            float gv = tanh_(a[j*4 + 2]);
            float ov = sigm(a[j*4 + 3]);
            c[j] = fv * c[j] + iv * gv;
            hB[(j0 + j) * Bb + b] = ov * tanh_(c[j]);
        }

        // ---- grid barrier (skip after last step; kernel boundary syncs for fc)
        if (t < Tt - 1) {
            __threadfence();                 // release h writes
            __syncthreads();
            if (tid == 0) {
                atomicAdd(&g_count, 1u);
                unsigned target = (unsigned)(t + 1) * gridDim.x;
                while (*((volatile unsigned*)&g_count) < target) { /* spin */ }
            }
            __syncthreads();
            __threadfence();                 // acquire before next step's h reads
        }
    }
}

// ---------- final FC: out[b] = h_T[:,b] . W_fc + b_fc ----------
__global__ void fc_kernel(const float* __restrict__ W_fc,
                          const float* __restrict__ b_fc,
                          float* __restrict__ out) {
    int b = threadIdx.x;
    float s = 0.f;
    #pragma unroll 16
    for (int k = 0; k < Hh; k++)
        s += g_h[0][k][b] * W_fc[k];        // final h lands in buffer 0 (T even)
    out[b] = s + b_fc[0];
}

extern "C" void kernel_launch(void* const* d_in, const int* in_sizes, int n_in,
                              void* d_out, int out_size) {
    const float* x    = (const float*)d_in[0];
    const float* W_ih = (const float*)d_in[1];
    const float* W_hh = (const float*)d_in[2];
    const float* b_ih = (const float*)d_in[3];
    const float* b_hh = (const float*)d_in[4];
    const float* W_fc = (const float*)d_in[5];
    const float* b_fc = (const float*)d_in[6];
    float* out = (float*)d_out;

    init_kernel<<<128, 256>>>();
    lstm_kernel<<<NCTA, NTHR>>>(x, W_ih, W_hh, b_ih, b_hh);
    fc_kernel<<<1, Bb>>>(W_fc, b_fc, out);
}

// round 4
// speedup vs baseline: 3.7077x; 3.6848x over previous
#include <cuda_runtime.h>
#include <cuda_bf16.h>
#include <cstdint>

// ---------------- problem constants ----------------
#define Bb   256
#define Tt   512
#define Ii   64
#define Hh   512
#define NTHR 256

// SMEM layout offsets (from 1024-aligned base)
#define OFF_WHHI 0          // W_hh slice hi: [32 c][1024 B]
#define OFF_WHLO 32768
#define OFF_WXHI 65536      // W_ih slice hi: [32 c][128 B]
#define OFF_WXLO 69632
#define OFF_A0   73728      // A buffer 0: [hi 32KB][lo 32KB]
#define OFF_A1   139264
#define DSM_BYTES (204800 + 1024)

// ---------------- persistent device state ----------------
// h in "tile layout": [buf][half][kchunk][64KB], each 64KB = [hi: 128 rows x 256B swz][lo]
__device__ __align__(1024) unsigned char g_hblk[2][2][4][65536];
// x in tile layout: per (t, half): 32KB = [hi: 128 rows x 128B swz][lo]
__device__ __align__(1024) unsigned char g_xblk[Tt][2][32768];
__device__ float    g_hfinal[Bb][Hh];
__device__ unsigned g_cnt[2];

// ---------------- PTX helpers ----------------
__device__ __forceinline__ uint32_t smem_u32(const void* p) {
    uint32_t a;
    asm("{ .reg .u64 t; cvta.to.shared.u64 t, %1; cvt.u32.u64 %0, t; }" : "=r"(a) : "l"(p));
    return a;
}
#define MBARRIER_INIT(sa, cnt) \
    asm volatile("mbarrier.init.shared.b64 [%0], %1;" :: "r"((uint32_t)(sa)), "r"((uint32_t)(cnt)) : "memory")
#define MBAR_WAIT(sa, ph) do { \
    asm volatile("{\n\t.reg .pred P1;\n\tWL%=:\n\t" \
        "mbarrier.try_wait.parity.acquire.cta.shared::cta.b64 P1, [%0], %1, 0x989680;\n\t" \
        "@P1 bra.uni WD%=;\n\tbra.uni WL%=;\n\tWD%=:\n\t}" \
        :: "r"((uint32_t)(sa)), "r"((uint32_t)(ph)) : "memory"); \
} while (0)
#define FENCE_PROXY_ASYNC() asm volatile("fence.proxy.async.shared::cta;" ::: "memory")

__device__ __forceinline__ void tma_issue(uint32_t dst, const void* src, uint32_t bytes, uint32_t mbar) {
    asm volatile("mbarrier.arrive.expect_tx.shared.b64 _, [%0], %1;"
                 :: "r"(mbar), "r"(bytes) : "memory");
    asm volatile("cp.async.bulk.shared::cta.global.mbarrier::complete_tx::bytes [%0], [%1], %2, [%3];"
                 :: "r"(dst), "l"(src), "r"(bytes), "r"(mbar) : "memory");
}
__device__ __forceinline__ void ldsm4(uint32_t& a, uint32_t& b, uint32_t& c, uint32_t& d, uint32_t addr) {
    asm volatile("ldmatrix.sync.aligned.m8n8.x4.shared.b16 {%0,%1,%2,%3}, [%4];"
                 : "=r"(a), "=r"(b), "=r"(c), "=r"(d) : "r"(addr));
}
__device__ __forceinline__ void mma16816(float* c, uint32_t a0, uint32_t a1, uint32_t a2, uint32_t a3,
                                         uint32_t b0, uint32_t b1) {
    asm volatile("mma.sync.aligned.m16n8k16.row.col.f32.bf16.bf16.f32 "
                 "{%0,%1,%2,%3}, {%4,%5,%6,%7}, {%8,%9}, {%0,%1,%2,%3};"
                 : "+f"(c[0]), "+f"(c[1]), "+f"(c[2]), "+f"(c[3])
                 : "r"(a0), "r"(a1), "r"(a2), "r"(a3), "r"(b0), "r"(b1));
}

// ---------------- activations ----------------
__device__ __forceinline__ float sigm(float x) { return __fdividef(1.f, 1.f + __expf(-x)); }
__device__ __forceinline__ float tanh_(float x) {
    x = fminf(fmaxf(x, -15.f), 15.f);
    float e = __expf(2.f * x);
    return __fdividef(e - 1.f, e + 1.f);
}

// ---------------- chunk GEMM: 3-term split-bf16 via mma.sync ----------------
// A tile [128 rows x (NK*16) k] bf16 at Abase (hi) / Abase+128*RS (lo), rows RS bytes,
// 16B-chunk swizzle: chunkIdx ^ (row&7).  W rows WR bytes, same swizzle vs c.
template<int RS, int WR, int NK>
__device__ __forceinline__ void compute_chunk(uint32_t Abase, uint32_t Whi, uint32_t Wlo,
                                              int kw0, float (&acc)[4][4], int lane, int m0) {
    const int rA   = m0 + (lane & 15);
    const int kA   = lane >> 4;          // 0/1: k-half
    const int xr   = lane & 7;           // swizzle xor (row/col low bits)
    const int cB   = (lane & 7) + ((lane & 16) >> 1);   // B row for tiles 0/1
    const int kB   = (lane >> 3) & 1;
    const uint32_t dlo = Wlo - Whi;
#pragma unroll
    for (int s = 0; s < NK; s++) {
        const int kcA = s * 2;
        uint32_t aaddr = Abase + rA * RS + (((kcA + kA) ^ xr) << 4);
        uint32_t ah[4], al[4];
        ldsm4(ah[0], ah[1], ah[2], ah[3], aaddr);
        ldsm4(al[0], al[1], al[2], al[3], aaddr + RS * 128);
        const int kcW = kw0 + s * 2;
        uint32_t b01 = Whi + cB * WR + (((kcW + kB) ^ xr) << 4);
        uint32_t bh[8], bl[8];
        ldsm4(bh[0], bh[1], bh[2], bh[3], b01);
        ldsm4(bh[4], bh[5], bh[6], bh[7], b01 + 16 * WR);
        ldsm4(bl[0], bl[1], bl[2], bl[3], b01 + dlo);
        ldsm4(bl[4], bl[5], bl[6], bl[7], b01 + dlo + 16 * WR);
#pragma unroll
        for (int ti = 0; ti < 4; ti++) {
            mma16816(acc[ti], ah[0], ah[1], ah[2], ah[3], bh[2 * ti], bh[2 * ti + 1]);
            mma16816(acc[ti], ah[0], ah[1], ah[2], ah[3], bl[2 * ti], bl[2 * ti + 1]);
            mma16816(acc[ti], al[0], al[1], al[2], al[3], bh[2 * ti], bh[2 * ti + 1]);
        }
    }
}

// ---------------- init: zero h buf0, reset barriers, split x into tile layout ----------------
__global__ void init_kernel(const float* __restrict__ x) {
    int idx = blockIdx.x * blockDim.x + threadIdx.x;
    int stride = gridDim.x * blockDim.x;
    // zero h buffer 0 (both halves, hi+lo): 512KB
    uint32_t* hz = reinterpret_cast<uint32_t*>(&g_hblk[0][0][0][0]);
    for (int i = idx; i < 2 * 4 * 65536 / 4; i += stride) hz[i] = 0u;
    // x convert: x[b][t][i] -> g_xblk[t][half] tile layout, hi/lo split
    for (int i = idx; i < Bb * Tt * Ii; i += stride) {
        int ii = i & 63;
        int t  = (i >> 6) & 511;
        int b  = i >> 15;
        float v = x[i];
        __nv_bfloat16 hi = __float2bfloat16(v);
        __nv_bfloat16 lo = __float2bfloat16(v - __bfloat162float(hi));
        int half = b >> 7, m = b & 127;
        unsigned off = (unsigned)m * 128u + ((((unsigned)ii >> 3) ^ (m & 7)) << 4) + (ii & 7) * 2u;
        *reinterpret_cast<__nv_bfloat16*>(&g_xblk[t][half][off])         = hi;
        *reinterpret_cast<__nv_bfloat16*>(&g_xblk[t][half][off + 16384]) = lo;
    }
    if (idx < 2) g_cnt[idx] = 0u;
}

// ---------------- persistent LSTM (mma.sync tensor cores) ----------------
__global__ void __launch_bounds__(NTHR, 1) lstm_kernel(
    const float* __restrict__ W_ih,   // [2048, 64]
    const float* __restrict__ W_hh,   // [2048, 512]
    const float* __restrict__ b_ih,
    const float* __restrict__ b_hh)
{
    extern __shared__ char dsm[];
    __shared__ __align__(8) unsigned long long s_mbar[2];
    __shared__ float s_bias[32];

    const int tid  = threadIdx.x;
    const int lane = tid & 31;
    const int wid  = tid >> 5;
    const int m0   = wid * 16;
    const int half = blockIdx.x >> 6;       // batch half
    const int nc   = blockIdx.x & 63;       // column CTA: gate cols [nc*32, nc*32+32)

    uint32_t raw = smem_u32(dsm);
    uint32_t base = (raw + 1023u) & ~1023u;
    char* bptr = dsm + (base - raw);

    // ---- stage W slices (once), split hi/lo, swizzled ----
    // col c = jl*4 + gate  (jl in [0,8)), global gate row = gate*512 + nc*8 + jl
    for (int idx = tid; idx < 32 * Hh; idx += NTHR) {
        int c = idx >> 9, k = idx & 511;
        int row = (c & 3) * Hh + nc * 8 + (c >> 2);
        float w = W_hh[(size_t)row * Hh + k];
        __nv_bfloat16 hi = __float2bfloat16(w);
        __nv_bfloat16 lo = __float2bfloat16(w - __bfloat162float(hi));
        unsigned off = (unsigned)c * 1024u + ((((unsigned)k >> 3) ^ (c & 7)) << 4) + (k & 7) * 2u;
        *reinterpret_cast<__nv_bfloat16*>(bptr + OFF_WHHI + off) = hi;
        *reinterpret_cast<__nv_bfloat16*>(bptr + OFF_WHLO + off) = lo;
    }
    for (int idx = tid; idx < 32 * Ii; idx += NTHR) {
        int c = idx >> 6, k = idx & 63;
        int row = (c & 3) * Hh + nc * 8 + (c >> 2);
        float w = W_ih[(size_t)row * Ii + k];
        __nv_bfloat16 hi = __float2bfloat16(w);
        __nv_bfloat16 lo = __float2bfloat16(w - __bfloat162float(hi));
        unsigned off = (unsigned)c * 128u + ((((unsigned)k >> 3) ^ (c & 7)) << 4) + (k & 7) * 2u;
        *reinterpret_cast<__nv_bfloat16*>(bptr + OFF_WXHI + off) = hi;
        *reinterpret_cast<__nv_bfloat16*>(bptr + OFF_WXLO + off) = lo;
    }
    if (tid < 32) {
        int row = (tid & 3) * Hh + nc * 8 + (tid >> 2);
        s_bias[tid] = b_ih[row] + b_hh[row];
    }
    if (tid == 0) { MBARRIER_INIT(smem_u32(&s_mbar[0]), 1); MBARRIER_INIT(smem_u32(&s_mbar[1]), 1); }
    __syncthreads();

    const uint32_t mb0 = smem_u32(&s_mbar[0]);
    const uint32_t mb1 = smem_u32(&s_mbar[1]);
    const uint32_t WhHi = base + OFF_WHHI, WhLo = base + OFF_WHLO;
    const uint32_t WxHi = base + OFF_WXHI, WxLo = base + OFF_WXLO;
    const uint32_t Abuf[2] = { base + OFF_A0, base + OFF_A1 };
    float* scr = reinterpret_cast<float*>(bptr + OFF_A0);   // epi scratch aliases A0

    // per-thread epilogue constants
    const int em = tid & 127, eg = tid >> 7;
    float bia[16];
#pragma unroll
    for (int q = 0; q < 16; q++) bia[q] = s_bias[eg * 16 + q];

    float cs[4] = {0.f, 0.f, 0.f, 0.f};   // cell state for (em, 4 units)
    int ph0 = 0, ph1 = 0;

#pragma unroll 1
    for (int t = 0; t < Tt; t++) {
        const int rb = t & 1, wb = rb ^ 1;
        const unsigned char (*hsrc)[65536] = g_hblk[rb][half];

        if (tid == 0) {
            FENCE_PROXY_ASYNC();          // generic scratch reads (prev step) -> async writes
            tma_issue(Abuf[0], &hsrc[0][0], 65536, mb0);
            tma_issue(Abuf[1], &hsrc[1][0], 65536, mb1);
        }

        float acc[4][4];
#pragma unroll
        for (int a = 0; a < 4; a++)
#pragma unroll
            for (int bq = 0; bq < 4; bq++) acc[a][bq] = 0.f;

#pragma unroll 1
        for (int kc = 0; kc < 4; kc++) {
            if (kc & 1) { MBAR_WAIT(mb1, ph1); ph1 ^= 1; }
            else        { MBAR_WAIT(mb0, ph0); ph0 ^= 1; }
            compute_chunk<256, 1024, 8>(Abuf[kc & 1], WhHi, WhLo, kc * 16, acc, lane, m0);
            __syncthreads();
            if (tid == 0) {
                if (kc < 2)       tma_issue(Abuf[kc], &hsrc[kc + 2][0], 65536, kc ? mb1 : mb0);
                else if (kc == 2) tma_issue(Abuf[0], &g_xblk[t][half][0], 32768, mb0);
            }
        }
        // x chunk (K=64)
        MBAR_WAIT(mb0, ph0); ph0 ^= 1;
        compute_chunk<128, 128, 4>(Abuf[0], WxHi, WxLo, 0, acc, lane, m0);
        __syncthreads();   // everyone done with A0 before scratch overwrite

        // ---- epilogue: C frags -> scratch [128][36] ----
        {
            const int r0 = m0 + (lane >> 2), cb = (lane & 3) * 2;
#pragma unroll
            for (int ti = 0; ti < 4; ti++) {
                *reinterpret_cast<float2*>(&scr[r0 * 36 + ti * 8 + cb]       ) = make_float2(acc[ti][0], acc[ti][1]);
                *reinterpret_cast<float2*>(&scr[(r0 + 8) * 36 + ti * 8 + cb] ) = make_float2(acc[ti][2], acc[ti][3]);
            }
        }
        __syncthreads();

        // ---- cell update: thread (em, eg) owns 4 units ----
        {
            __align__(8) __nv_bfloat16 hh[4], hl[4];
            float hv4[4];
#pragma unroll
            for (int q = 0; q < 4; q++) {
                float4 v = *reinterpret_cast<float4*>(&scr[em * 36 + eg * 16 + q * 4]);
                float iv = sigm(v.x + bia[q * 4 + 0]);
                float fv = sigm(v.y + bia[q * 4 + 1]);
                float gv = tanh_(v.z + bia[q * 4 + 2]);
                float ov = sigm(v.w + bia[q * 4 + 3]);
                cs[q] = fv * cs[q] + iv * gv;
                float hv = ov * tanh_(cs[q]);
                hv4[q] = hv;
                hh[q] = __float2bfloat16(hv);
                hl[q] = __float2bfloat16(hv - __bfloat162float(hh[q]));
            }
            unsigned char* dst = &g_hblk[wb][half][nc >> 4][0]
                               + em * 256 + (((nc & 15) ^ (em & 7)) << 4) + eg * 8;
            *reinterpret_cast<uint2*>(dst)          = *reinterpret_cast<uint2*>(hh);
            *reinterpret_cast<uint2*>(dst + 32768)  = *reinterpret_cast<uint2*>(hl);
            if (t == Tt - 1)
                *reinterpret_cast<float4*>(&g_hfinal[half * 128 + em][nc * 8 + eg * 4]) =
                    make_float4(hv4[0], hv4[1], hv4[2], hv4[3]);
        }

        // ---- per-half barrier (64 CTAs) ----
        if (t < Tt - 1) {
            __threadfence();
            __syncthreads();
            if (tid == 0) {
                atomicAdd(&g_cnt[half], 1u);
                unsigned target = (unsigned)(t + 1) * 64u;
                while (*reinterpret_cast<volatile unsigned*>(&g_cnt[half]) < target) { }
            }
            __syncthreads();
        }
    }
}

// ---------------- final FC ----------------
__global__ void fc_kernel(const float* __restrict__ W_fc,
                          const float* __restrict__ b_fc,
                          float* __restrict__ out) {
    int b = threadIdx.x;
    float s = 0.f;
#pragma unroll 8
    for (int k = 0; k < Hh; k++) s += g_hfinal[b][k] * W_fc[k];
    out[b] = s + b_fc[0];
}

extern "C" void kernel_launch(void* const* d_in, const int* in_sizes, int n_in,
                              void* d_out, int out_size) {
    const float* x    = (const float*)d_in[0];
    const float* W_ih = (const float*)d_in[1];
    const float* W_hh = (const float*)d_in[2];
    const float* b_ih = (const float*)d_in[3];
    const float* b_hh = (const float*)d_in[4];
    const float* W_fc = (const float*)d_in[5];
    const float* b_fc = (const float*)d_in[6];
    float* out = (float*)d_out;

    cudaFuncSetAttribute(lstm_kernel, cudaFuncAttributeMaxDynamicSharedMemorySize, DSM_BYTES);

    init_kernel<<<2048, 256>>>(x);
    lstm_kernel<<<128, NTHR, DSM_BYTES>>>(W_ih, W_hh, b_ih, b_hh);
    fc_kernel<<<1, Bb>>>(W_fc, b_fc, out);
}

// round 6
// speedup vs baseline: 3.9672x; 1.0700x over previous
#include <cuda_runtime.h>
#include <cuda_bf16.h>
#include <cstdint>

// ---------------- problem constants ----------------
#define Bb   256
#define Tt   512
#define Ii   64
#define Hh   512
#define NTHR 256     // 8 warps: warp grid 4(M) x 2(N), warp tile M16 x N32

// SMEM layout offsets (from 1024-aligned base)
#define OFF_WHHI 0            // W_hh slice hi: [64 c][1024 B]
#define OFF_WHLO 65536
#define OFF_WXHI 131072       // W_ih slice hi: [64 c][128 B]
#define OFF_WXLO 139264
#define OFF_A0   147456       // h chunk buf 0: [hi 16KB][lo 16KB]
#define OFF_A1   180224
#define OFF_XB   212992       // x buf: [hi 8KB][lo 8KB]
#define DSM_BYTES (229376 + 1024)

// ---------------- persistent device state ----------------
// h tile layout: [buf][group][kchunk][32KB]; group = half*2 + mtile (64 batch rows)
// each 32KB chunk = [hi: 64 rows x 256B swz][lo: same]
__device__ __align__(1024) unsigned char g_hblk[2][4][4][32768];
// x tile layout: [t][group][16KB] = [hi: 64 rows x 128B swz][lo]
__device__ __align__(1024) unsigned char g_xblk[Tt][4][16384];
__device__ float    g_hfinal[Bb][Hh];
__device__ unsigned g_cnt[4][32];     // one cacheline per group

// ---------------- PTX helpers ----------------
__device__ __forceinline__ uint32_t smem_u32(const void* p) {
    uint32_t a;
    asm("{ .reg .u64 t; cvta.to.shared.u64 t, %1; cvt.u32.u64 %0, t; }" : "=r"(a) : "l"(p));
    return a;
}
#define MBARRIER_INIT(sa, cnt) \
    asm volatile("mbarrier.init.shared.b64 [%0], %1;" :: "r"((uint32_t)(sa)), "r"((uint32_t)(cnt)) : "memory")
#define MBAR_WAIT(sa, ph) do { \
    asm volatile("{\n\t.reg .pred P1;\n\tWL%=:\n\t" \
        "mbarrier.try_wait.parity.acquire.cta.shared::cta.b64 P1, [%0], %1, 0x989680;\n\t" \
        "@P1 bra.uni WD%=;\n\tbra.uni WL%=;\n\tWD%=:\n\t}" \
        :: "r"((uint32_t)(sa)), "r"((uint32_t)(ph)) : "memory"); \
} while (0)
#define FENCE_PROXY_ASYNC() asm volatile("fence.proxy.async.shared::cta;" ::: "memory")

__device__ __forceinline__ void tma_issue(uint32_t dst, const void* src, uint32_t bytes, uint32_t mbar) {
    asm volatile("mbarrier.arrive.expect_tx.shared.b64 _, [%0], %1;"
                 :: "r"(mbar), "r"(bytes) : "memory");
    asm volatile("cp.async.bulk.shared::cta.global.mbarrier::complete_tx::bytes [%0], [%1], %2, [%3];"
                 :: "r"(dst), "l"(src), "r"(bytes), "r"(mbar) : "memory");
}
__device__ __forceinline__ void ldsm4(uint32_t& a, uint32_t& b, uint32_t& c, uint32_t& d, uint32_t addr) {
    asm volatile("ldmatrix.sync.aligned.m8n8.x4.shared.b16 {%0,%1,%2,%3}, [%4];"
                 : "=r"(a), "=r"(b), "=r"(c), "=r"(d) : "r"(addr));
}
__device__ __forceinline__ void mma16816(float* c, uint32_t a0, uint32_t a1, uint32_t a2, uint32_t a3,
                                         uint32_t b0, uint32_t b1) {
    asm volatile("mma.sync.aligned.m16n8k16.row.col.f32.bf16.bf16.f32 "
                 "{%0,%1,%2,%3}, {%4,%5,%6,%7}, {%8,%9}, {%0,%1,%2,%3};"
                 : "+f"(c[0]), "+f"(c[1]), "+f"(c[2]), "+f"(c[3])
                 : "r"(a0), "r"(a1), "r"(a2), "r"(a3), "r"(b0), "r"(b1));
}

// ---------------- activations ----------------
__device__ __forceinline__ float sigm(float x) { return __fdividef(1.f, 1.f + __expf(-x)); }
__device__ __forceinline__ float tanh_(float x) {
    x = fminf(fmaxf(x, -15.f), 15.f);
    float e = __expf(2.f * x);
    return __fdividef(e - 1.f, e + 1.f);
}

// ---------------- chunk GEMM: 3-term split-bf16 via mma.sync ----------------
// A tile [64 rows x (NK*16) k] bf16 at Abase (hi), lo at Abase+LOFF, rows RS bytes.
// W rows WR bytes (base already offset to this warp's N=32 slab). 16B-chunk swizzle.
template<int RS, int WR, int NK, int LOFF>
__device__ __forceinline__ void compute_chunk(uint32_t Abase, uint32_t Whi, uint32_t Wlo,
                                              int kw0, float (&acc)[4][4], int lane, int m0) {
    const int rA = m0 + (lane & 15);
    const int kA = lane >> 4;
    const int xr = lane & 7;
    const int cB = (lane & 7) + ((lane & 16) >> 1);
    const int kB = (lane >> 3) & 1;
    const uint32_t dlo = Wlo - Whi;
#pragma unroll
    for (int s = 0; s < NK; s++) {
        const int kcA = s * 2;
        uint32_t aaddr = Abase + rA * RS + (((kcA + kA) ^ xr) << 4);
        uint32_t ah[4], al[4];
        ldsm4(ah[0], ah[1], ah[2], ah[3], aaddr);
        ldsm4(al[0], al[1], al[2], al[3], aaddr + LOFF);
        const int kcW = kw0 + s * 2;
        uint32_t b01 = Whi + cB * WR + (((kcW + kB) ^ xr) << 4);
        uint32_t bh[8], bl[8];
        ldsm4(bh[0], bh[1], bh[2], bh[3], b01);
        ldsm4(bh[4], bh[5], bh[6], bh[7], b01 + 16 * WR);
        ldsm4(bl[0], bl[1], bl[2], bl[3], b01 + dlo);
        ldsm4(bl[4], bl[5], bl[6], bl[7], b01 + dlo + 16 * WR);
#pragma unroll
        for (int ti = 0; ti < 4; ti++) {
            mma16816(acc[ti], ah[0], ah[1], ah[2], ah[3], bh[2 * ti], bh[2 * ti + 1]);
            mma16816(acc[ti], ah[0], ah[1], ah[2], ah[3], bl[2 * ti], bl[2 * ti + 1]);
            mma16816(acc[ti], al[0], al[1], al[2], al[3], bh[2 * ti], bh[2 * ti + 1]);
        }
    }
}

// ---------------- init: zero h buf0, reset barriers, split x into tile layout ----------------
__global__ void init_kernel(const float* __restrict__ x) {
    int idx = blockIdx.x * blockDim.x + threadIdx.x;
    int stride = gridDim.x * blockDim.x;
    uint32_t* hz = reinterpret_cast<uint32_t*>(&g_hblk[0][0][0][0]);
    for (int i = idx; i < 4 * 4 * 32768 / 4; i += stride) hz[i] = 0u;
    for (int i = idx; i < Bb * Tt * Ii; i += stride) {
        int ii = i & 63;
        int t  = (i >> 6) & 511;
        int b  = i >> 15;
        float v = x[i];
        __nv_bfloat16 hi = __float2bfloat16(v);
        __nv_bfloat16 lo = __float2bfloat16(v - __bfloat162float(hi));
        int grp = b >> 6, m = b & 63;
        unsigned off = (unsigned)m * 128u + ((((unsigned)ii >> 3) ^ (m & 7)) << 4) + (ii & 7) * 2u;
        *reinterpret_cast<__nv_bfloat16*>(&g_xblk[t][grp][off])        = hi;
        *reinterpret_cast<__nv_bfloat16*>(&g_xblk[t][grp][off + 8192]) = lo;
    }
    if (idx < 4) g_cnt[idx][0] = 0u;
}

// ---------------- persistent LSTM (mma.sync tensor cores) ----------------
__global__ void __launch_bounds__(NTHR, 1) lstm_kernel(
    const float* __restrict__ W_ih,   // [2048, 64]
    const float* __restrict__ W_hh,   // [2048, 512]
    const float* __restrict__ b_ih,
    const float* __restrict__ b_hh)
{
    extern __shared__ char dsm[];
    __shared__ __align__(8) unsigned long long s_mbar[3];
    __shared__ float s_bias[64];

    const int tid  = threadIdx.x;
    const int lane = tid & 31;
    const int wid  = tid >> 5;
    const int m0   = (wid >> 1) * 16;       // warp M offset within 64 rows
    const int n0   = (wid & 1) * 32;        // warp N offset within 64 cols
    const int grp  = blockIdx.x >> 5;       // group = half*2 + mtile (owns 64 batch rows)
    const int nc   = blockIdx.x & 31;       // column CTA: gate cols [nc*64, nc*64+64) -> 16 units

    uint32_t raw = smem_u32(dsm);
    uint32_t base = (raw + 1023u) & ~1023u;
    char* bptr = dsm + (base - raw);

    // ---- stage W slices (once), split hi/lo, swizzled ----
    // col c = jl*4 + gate (jl in [0,16)); global gate row = gate*512 + nc*16 + jl
    for (int idx = tid; idx < 64 * Hh; idx += NTHR) {
        int c = idx >> 9, k = idx & 511;
        int row = (c & 3) * Hh + nc * 16 + (c >> 2);
        float w = W_hh[(size_t)row * Hh + k];
        __nv_bfloat16 hi = __float2bfloat16(w);
        __nv_bfloat16 lo = __float2bfloat16(w - __bfloat162float(hi));
        unsigned off = (unsigned)c * 1024u + ((((unsigned)k >> 3) ^ (c & 7)) << 4) + (k & 7) * 2u;
        *reinterpret_cast<__nv_bfloat16*>(bptr + OFF_WHHI + off) = hi;
        *reinterpret_cast<__nv_bfloat16*>(bptr + OFF_WHLO + off) = lo;
    }
    for (int idx = tid; idx < 64 * Ii; idx += NTHR) {
        int c = idx >> 6, k = idx & 63;
        int row = (c & 3) * Hh + nc * 16 + (c >> 2);
        float w = W_ih[(size_t)row * Ii + k];
        __nv_bfloat16 hi = __float2bfloat16(w);
        __nv_bfloat16 lo = __float2bfloat16(w - __bfloat162float(hi));
        unsigned off = (unsigned)c * 128u + ((((unsigned)k >> 3) ^ (c & 7)) << 4) + (k & 7) * 2u;
        *reinterpret_cast<__nv_bfloat16*>(bptr + OFF_WXHI + off) = hi;
        *reinterpret_cast<__nv_bfloat16*>(bptr + OFF_WXLO + off) = lo;
    }
    if (tid < 64) {
        int row = (tid & 3) * Hh + nc * 16 + (tid >> 2);
        s_bias[tid] = b_ih[row] + b_hh[row];
    }
    if (tid == 0) {
        MBARRIER_INIT(smem_u32(&s_mbar[0]), 1);
        MBARRIER_INIT(smem_u32(&s_mbar[1]), 1);
        MBARRIER_INIT(smem_u32(&s_mbar[2]), 1);
    }
    __syncthreads();

    const uint32_t mb0 = smem_u32(&s_mbar[0]);
    const uint32_t mb1 = smem_u32(&s_mbar[1]);
    const uint32_t mb2 = smem_u32(&s_mbar[2]);
    // warp's W base (N=32 slab)
    const uint32_t WhHiW = base + OFF_WHHI + n0 * 1024;
    const uint32_t WhLoW = base + OFF_WHLO + n0 * 1024;
    const uint32_t WxHiW = base + OFF_WXHI + n0 * 128;
    const uint32_t WxLoW = base + OFF_WXLO + n0 * 128;
    const uint32_t Abuf[2] = { base + OFF_A0, base + OFF_A1 };
    const uint32_t XB = base + OFF_XB;
    float* scr = reinterpret_cast<float*>(bptr + OFF_A0);   // epi scratch aliases A0 (17.4KB<32KB)

    // per-thread epilogue constants: row em, unit group eg (4 units)
    const int em = tid & 63, eg = tid >> 6;
    float bia[16];
#pragma unroll
    for (int q = 0; q < 16; q++) bia[q] = s_bias[eg * 16 + q];

    // precomputed h output address (layout matches TMA chunk format)
    const int u0 = nc * 16 + eg * 4;
    const int kcb = u0 >> 7, ucol = u0 & 127;
    const unsigned hoff = (unsigned)em * 256u + ((((unsigned)ucol >> 3) ^ (em & 7)) << 4) + (ucol & 7) * 2u;

    float cs[4] = {0.f, 0.f, 0.f, 0.f};
    int ph0 = 0, ph1 = 0, ph2 = 0;
    unsigned* cnt = &g_cnt[grp][0];

#pragma unroll 1
    for (int t = 0; t < Tt; t++) {
        const int rb = t & 1, wb = rb ^ 1;
        const unsigned char (*hsrc)[32768] = g_hblk[rb][grp];

        if (tid == 0) {
            FENCE_PROXY_ASYNC();
            tma_issue(Abuf[0], &hsrc[0][0], 32768, mb0);
            tma_issue(Abuf[1], &hsrc[1][0], 32768, mb1);
            tma_issue(XB, &g_xblk[t][grp][0], 16384, mb2);
        }

        float acc[4][4];
#pragma unroll
        for (int a = 0; a < 4; a++)
#pragma unroll
            for (int bq = 0; bq < 4; bq++) acc[a][bq] = 0.f;

#pragma unroll 1
        for (int kc = 0; kc < 4; kc++) {
            if (kc & 1) { MBAR_WAIT(mb1, ph1); ph1 ^= 1; }
            else        { MBAR_WAIT(mb0, ph0); ph0 ^= 1; }
            compute_chunk<256, 1024, 8, 16384>(Abuf[kc & 1], WhHiW, WhLoW, kc * 16, acc, lane, m0);
            __syncthreads();
            if (tid == 0 && kc < 2) {
                FENCE_PROXY_ASYNC();
                tma_issue(Abuf[kc], &hsrc[kc + 2][0], 32768, kc ? mb1 : mb0);
            }
        }
        // x chunk (K=64), buffer loaded since step start
        MBAR_WAIT(mb2, ph2); ph2 ^= 1;
        compute_chunk<128, 128, 4, 8192>(XB, WxHiW, WxLoW, 0, acc, lane, m0);
        __syncthreads();   // all ldmatrix reads of A0 done before scratch overwrite

        // ---- C frags -> scratch [64][68] ----
        {
            const int r0 = m0 + (lane >> 2), cb = n0 + (lane & 3) * 2;
#pragma unroll
            for (int ti = 0; ti < 4; ti++) {
                *reinterpret_cast<float2*>(&scr[r0 * 68 + ti * 8 + cb])       = make_float2(acc[ti][0], acc[ti][1]);
                *reinterpret_cast<float2*>(&scr[(r0 + 8) * 68 + ti * 8 + cb]) = make_float2(acc[ti][2], acc[ti][3]);
            }
        }
        __syncthreads();

        // ---- cell update: thread (em, eg) owns 4 units ----
        {
            __align__(8) __nv_bfloat16 hh[4], hl[4];
            float hv4[4];
#pragma unroll
            for (int q = 0; q < 4; q++) {
                float4 v = *reinterpret_cast<float4*>(&scr[em * 68 + eg * 16 + q * 4]);
                float iv = sigm(v.x + bia[q * 4 + 0]);
                float fv = sigm(v.y + bia[q * 4 + 1]);
                float gv = tanh_(v.z + bia[q * 4 + 2]);
                float ov = sigm(v.w + bia[q * 4 + 3]);
                cs[q] = fv * cs[q] + iv * gv;
                float hv = ov * tanh_(cs[q]);
                hv4[q] = hv;
                hh[q] = __float2bfloat16(hv);
                hl[q] = __float2bfloat16(hv - __bfloat162float(hh[q]));
            }
            unsigned char* dst = &g_hblk[wb][grp][kcb][0] + hoff;
            *reinterpret_cast<uint2*>(dst)         = *reinterpret_cast<uint2*>(hh);
            *reinterpret_cast<uint2*>(dst + 16384) = *reinterpret_cast<uint2*>(hl);
            if (t == Tt - 1)
                *reinterpret_cast<float4*>(&g_hfinal[grp * 64 + em][u0]) =
                    make_float4(hv4[0], hv4[1], hv4[2], hv4[3]);
        }

        // ---- group barrier (32 CTAs): release-add + acquire-spin (w/ nanosleep) ----
        if (t < Tt - 1) {
            __syncthreads();
            if (tid == 0) {
                asm volatile("red.release.gpu.global.add.u32 [%0], %1;"
                             :: "l"(cnt), "r"(1u) : "memory");
                unsigned target = (unsigned)(t + 1) * 32u, v;
                while (true) {
                    asm volatile("ld.acquire.gpu.global.u32 %0, [%1];" : "=r"(v) : "l"(cnt));
                    if (v >= target) break;
                    asm volatile("nanosleep.u32 64;");
                }
            }
            __syncthreads();
        }
    }
}

// ---------------- final FC ----------------
__global__ void fc_kernel(const float* __restrict__ W_fc,
                          const float* __restrict__ b_fc,
                          float* __restrict__ out) {
    int b = threadIdx.x;
    float s = 0.f;
#pragma unroll 8
    for (int k = 0; k < Hh; k++) s += g_hfinal[b][k] * W_fc[k];
    out[b] = s + b_fc[0];
}

extern "C" void kernel_launch(void* const* d_in, const int* in_sizes, int n_in,
                              void* d_out, int out_size) {
    const float* x    = (const float*)d_in[0];
    const float* W_ih = (const float*)d_in[1];
    const float* W_hh = (const float*)d_in[2];
    const float* b_ih = (const float*)d_in[3];
    const float* b_hh = (const float*)d_in[4];
    const float* W_fc = (const float*)d_in[5];
    const float* b_fc = (const float*)d_in[6];
    float* out = (float*)d_out;

    cudaFuncSetAttribute(lstm_kernel, cudaFuncAttributeMaxDynamicSharedMemorySize, DSM_BYTES);

    init_kernel<<<1024, 256>>>(x);
    lstm_kernel<<<128, NTHR, DSM_BYTES>>>(W_ih, W_hh, b_ih, b_hh);
    fc_kernel<<<1, Bb>>>(W_fc, b_fc, out);
}

// round 7
// speedup vs baseline: 4.0914x; 1.0313x over previous
#include <cuda_runtime.h>
#include <cuda_bf16.h>
#include <cstdint>

// ---------------- problem constants ----------------
#define Bb   256
#define Tt   512
#define Ii   64
#define Hh   512
#define NTHR 288     // 8 compute warps (M4 x N2, warp tile M16 x N32) + 1 DMA warp

// SMEM layout offsets (from 1024-aligned base)
#define OFF_WHHI 0            // W_hh slice hi: [64 c][1024 B]
#define OFF_WHLO 65536
#define OFF_WXHI 131072       // W_ih slice hi: [64 c][128 B]
#define OFF_WXLO 139264
#define OFF_A0   147456       // h chunk buf 0: [hi 16KB][lo 16KB]
#define OFF_A1   180224
#define OFF_XB   212992       // x buf: [hi 8KB][lo 8KB]
#define DSM_BYTES (229376 + 1024)

// ---------------- persistent device state ----------------
// h tile layout: [buf][group][kchunk][32KB]; group = half*2 + mtile (64 batch rows)
// each 32KB chunk = [hi: 64 rows x 256B swz][lo: same]
__device__ __align__(1024) unsigned char g_hblk[2][4][4][32768];
// x tile layout: [t][group][16KB] = [hi: 64 rows x 128B swz][lo]
__device__ __align__(1024) unsigned char g_xblk[Tt][4][16384];
__device__ float    g_hfinal[Bb][Hh];
__device__ unsigned g_cnt[4][4][16];   // [group][kchunk], padded to 64B

// ---------------- PTX helpers ----------------
__device__ __forceinline__ uint32_t smem_u32(const void* p) {
    uint32_t a;
    asm("{ .reg .u64 t; cvta.to.shared.u64 t, %1; cvt.u32.u64 %0, t; }" : "=r"(a) : "l"(p));
    return a;
}
#define MBARRIER_INIT(sa, cnt) \
    asm volatile("mbarrier.init.shared.b64 [%0], %1;" :: "r"((uint32_t)(sa)), "r"((uint32_t)(cnt)) : "memory")
#define MBARRIER_ARRIVE(sa) \
    asm volatile("mbarrier.arrive.shared.b64 _, [%0];" :: "r"((uint32_t)(sa)) : "memory")
#define MBAR_WAIT(sa, ph) do { \
    asm volatile("{\n\t.reg .pred P1;\n\tWL%=:\n\t" \
        "mbarrier.try_wait.parity.acquire.cta.shared::cta.b64 P1, [%0], %1, 0x989680;\n\t" \
        "@P1 bra.uni WD%=;\n\tbra.uni WL%=;\n\tWD%=:\n\t}" \
        :: "r"((uint32_t)(sa)), "r"((uint32_t)(ph)) : "memory"); \
} while (0)
#define FENCE_PROXY_ASYNC() asm volatile("fence.proxy.async;" ::: "memory")

__device__ __forceinline__ void tma_issue(uint32_t dst, const void* src, uint32_t bytes, uint32_t mbar) {
    asm volatile("mbarrier.arrive.expect_tx.shared.b64 _, [%0], %1;"
                 :: "r"(mbar), "r"(bytes) : "memory");
    asm volatile("cp.async.bulk.shared::cta.global.mbarrier::complete_tx::bytes [%0], [%1], %2, [%3];"
                 :: "r"(dst), "l"(src), "r"(bytes), "r"(mbar) : "memory");
}
__device__ __forceinline__ void ldsm4(uint32_t& a, uint32_t& b, uint32_t& c, uint32_t& d, uint32_t addr) {
    asm volatile("ldmatrix.sync.aligned.m8n8.x4.shared.b16 {%0,%1,%2,%3}, [%4];"
                 : "=r"(a), "=r"(b), "=r"(c), "=r"(d) : "r"(addr));
}
__device__ __forceinline__ void mma16816(float* c, uint32_t a0, uint32_t a1, uint32_t a2, uint32_t a3,
                                         uint32_t b0, uint32_t b1) {
    asm volatile("mma.sync.aligned.m16n8k16.row.col.f32.bf16.bf16.f32 "
                 "{%0,%1,%2,%3}, {%4,%5,%6,%7}, {%8,%9}, {%0,%1,%2,%3};"
                 : "+f"(c[0]), "+f"(c[1]), "+f"(c[2]), "+f"(c[3])
                 : "r"(a0), "r"(a1), "r"(a2), "r"(a3), "r"(b0), "r"(b1));
}
#define BAR_COMPUTE() asm volatile("bar.sync 1, 256;" ::: "memory")

// ---------------- activations ----------------
__device__ __forceinline__ float sigm(float x) { return __fdividef(1.f, 1.f + __expf(-x)); }
__device__ __forceinline__ float tanh_(float x) {
    x = fminf(fmaxf(x, -15.f), 15.f);
    float e = __expf(2.f * x);
    return __fdividef(e - 1.f, e + 1.f);
}

// ---------------- chunk GEMM: 3-term split-bf16 via mma.sync ----------------
template<int RS, int WR, int NK, int LOFF>
__device__ __forceinline__ void compute_chunk(uint32_t Abase, uint32_t Whi, uint32_t Wlo,
                                              int kw0, float (&acc)[4][4], int lane, int m0) {
    const int rA = m0 + (lane & 15);
    const int kA = lane >> 4;
    const int xr = lane & 7;
    const int cB = (lane & 7) + ((lane & 16) >> 1);
    const int kB = (lane >> 3) & 1;
    const uint32_t dlo = Wlo - Whi;
#pragma unroll
    for (int s = 0; s < NK; s++) {
        const int kcA = s * 2;
        uint32_t aaddr = Abase + rA * RS + (((kcA + kA) ^ xr) << 4);
        uint32_t ah[4], al[4];
        ldsm4(ah[0], ah[1], ah[2], ah[3], aaddr);
        ldsm4(al[0], al[1], al[2], al[3], aaddr + LOFF);
        const int kcW = kw0 + s * 2;
        uint32_t b01 = Whi + cB * WR + (((kcW + kB) ^ xr) << 4);
        uint32_t bh[8], bl[8];
        ldsm4(bh[0], bh[1], bh[2], bh[3], b01);
        ldsm4(bh[4], bh[5], bh[6], bh[7], b01 + 16 * WR);
        ldsm4(bl[0], bl[1], bl[2], bl[3], b01 + dlo);
        ldsm4(bl[4], bl[5], bl[6], bl[7], b01 + dlo + 16 * WR);
#pragma unroll
        for (int ti = 0; ti < 4; ti++) {
            mma16816(acc[ti], ah[0], ah[1], ah[2], ah[3], bh[2 * ti], bh[2 * ti + 1]);
            mma16816(acc[ti], ah[0], ah[1], ah[2], ah[3], bl[2 * ti], bl[2 * ti + 1]);
            mma16816(acc[ti], al[0], al[1], al[2], al[3], bh[2 * ti], bh[2 * ti + 1]);
        }
    }
}

// ---------------- init: zero h buf0, reset counters, split x into tile layout ----------------
__global__ void init_kernel(const float* __restrict__ x) {
    int idx = blockIdx.x * blockDim.x + threadIdx.x;
    int stride = gridDim.x * blockDim.x;
    uint32_t* hz = reinterpret_cast<uint32_t*>(&g_hblk[0][0][0][0]);
    for (int i = idx; i < 4 * 4 * 32768 / 4; i += stride) hz[i] = 0u;
    for (int i = idx; i < Bb * Tt * Ii; i += stride) {
        int ii = i & 63;
        int t  = (i >> 6) & 511;
        int b  = i >> 15;
        float v = x[i];
        __nv_bfloat16 hi = __float2bfloat16(v);
        __nv_bfloat16 lo = __float2bfloat16(v - __bfloat162float(hi));
        int grp = b >> 6, m = b & 63;
        unsigned off = (unsigned)m * 128u + ((((unsigned)ii >> 3) ^ (m & 7)) << 4) + (ii & 7) * 2u;
        *reinterpret_cast<__nv_bfloat16*>(&g_xblk[t][grp][off])        = hi;
        *reinterpret_cast<__nv_bfloat16*>(&g_xblk[t][grp][off + 8192]) = lo;
    }
    if (idx < 16) g_cnt[idx >> 2][idx & 3][0] = 0u;
}

// ---------------- persistent LSTM: warp-specialized, fine-grained dataflow ----------------
__global__ void __launch_bounds__(NTHR, 1) lstm_kernel(
    const float* __restrict__ W_ih,   // [2048, 64]
    const float* __restrict__ W_hh,   // [2048, 512]
    const float* __restrict__ b_ih,
    const float* __restrict__ b_hh)
{
    extern __shared__ char dsm[];
    // mbarriers: 0=f0 1=f1 2=fx 3=e0 4=e1 5=ex
    __shared__ __align__(8) unsigned long long s_mbar[6];
    __shared__ float s_bias[64];

    const int tid  = threadIdx.x;
    const int lane = tid & 31;
    const int wid  = tid >> 5;
    const int grp  = blockIdx.x >> 5;       // owns 64 batch rows
    const int nc   = blockIdx.x & 31;       // gate cols [nc*64, nc*64+64) -> 16 units

    uint32_t raw = smem_u32(dsm);
    uint32_t base = (raw + 1023u) & ~1023u;
    char* bptr = dsm + (base - raw);

    // ---- stage W slices (once), split hi/lo, swizzled ----
    for (int idx = tid; idx < 64 * Hh; idx += NTHR) {
        int c = idx >> 9, k = idx & 511;
        int row = (c & 3) * Hh + nc * 16 + (c >> 2);
        float w = W_hh[(size_t)row * Hh + k];
        __nv_bfloat16 hi = __float2bfloat16(w);
        __nv_bfloat16 lo = __float2bfloat16(w - __bfloat162float(hi));
        unsigned off = (unsigned)c * 1024u + ((((unsigned)k >> 3) ^ (c & 7)) << 4) + (k & 7) * 2u;
        *reinterpret_cast<__nv_bfloat16*>(bptr + OFF_WHHI + off) = hi;
        *reinterpret_cast<__nv_bfloat16*>(bptr + OFF_WHLO + off) = lo;
    }
    for (int idx = tid; idx < 64 * Ii; idx += NTHR) {
        int c = idx >> 6, k = idx & 63;
        int row = (c & 3) * Hh + nc * 16 + (c >> 2);
        float w = W_ih[(size_t)row * Ii + k];
        __nv_bfloat16 hi = __float2bfloat16(w);
        __nv_bfloat16 lo = __float2bfloat16(w - __bfloat162float(hi));
        unsigned off = (unsigned)c * 128u + ((((unsigned)k >> 3) ^ (c & 7)) << 4) + (k & 7) * 2u;
        *reinterpret_cast<__nv_bfloat16*>(bptr + OFF_WXHI + off) = hi;
        *reinterpret_cast<__nv_bfloat16*>(bptr + OFF_WXLO + off) = lo;
    }
    if (tid < 64) {
        int row = (tid & 3) * Hh + nc * 16 + (tid >> 2);
        s_bias[tid] = b_ih[row] + b_hh[row];
    }
    if (tid == 0) {
        MBARRIER_INIT(smem_u32(&s_mbar[0]), 1);   // full A0 (expect_tx)
        MBARRIER_INIT(smem_u32(&s_mbar[1]), 1);   // full A1
        MBARRIER_INIT(smem_u32(&s_mbar[2]), 1);   // full X
        MBARRIER_INIT(smem_u32(&s_mbar[3]), 8);   // empty A0 (8 compute warps)
        MBARRIER_INIT(smem_u32(&s_mbar[4]), 8);   // empty A1
        MBARRIER_INIT(smem_u32(&s_mbar[5]), 8);   // empty X
    }
    __syncthreads();

    const uint32_t f0 = smem_u32(&s_mbar[0]), f1 = smem_u32(&s_mbar[1]), fx = smem_u32(&s_mbar[2]);
    const uint32_t e0 = smem_u32(&s_mbar[3]), e1 = smem_u32(&s_mbar[4]), ex = smem_u32(&s_mbar[5]);
    const uint32_t Abuf[2] = { base + OFF_A0, base + OFF_A1 };
    const uint32_t XB = base + OFF_XB;

    // =========================== DMA warp ===========================
    if (wid == 8) {
        if (lane == 0) {
            volatile unsigned* cnt[4] = { &g_cnt[grp][0][0], &g_cnt[grp][1][0],
                                          &g_cnt[grp][2][0], &g_cnt[grp][3][0] };
            int pe0 = 1, pe1 = 1, pex = 1;
#pragma unroll 1
            for (int t = 0; t < Tt; t++) {
                const unsigned char (*hsrc)[32768] = g_hblk[t & 1][grp];
                const unsigned target = (unsigned)t * 8u;
                // x tile (no producer dependency)
                MBAR_WAIT(ex, pex); pex ^= 1;
                FENCE_PROXY_ASYNC();
                tma_issue(XB, &g_xblk[t][grp][0], 16384, fx);
                // h chunks 0..3, ring A0/A1
#pragma unroll
                for (int kc = 0; kc < 4; kc++) {
                    if (kc & 1) { MBAR_WAIT(e1, pe1); pe1 ^= 1; }
                    else        { MBAR_WAIT(e0, pe0); pe0 ^= 1; }
                    unsigned v;
                    while (true) {
                        asm volatile("ld.acquire.gpu.global.u32 %0, [%1];" : "=r"(v) : "l"(cnt[kc]));
                        if (v >= target) break;
                        asm volatile("nanosleep.u32 32;");
                    }
                    FENCE_PROXY_ASYNC();
                    tma_issue(Abuf[kc & 1], &hsrc[kc][0], 32768, (kc & 1) ? f1 : f0);
                }
            }
        }
        return;
    }

    // =========================== compute warps ===========================
    const int m0 = (wid >> 1) * 16;          // warp M offset within 64 rows
    const int n0 = (wid & 1) * 32;           // warp N offset within 64 cols
    const uint32_t WhHiW = base + OFF_WHHI + n0 * 1024;
    const uint32_t WhLoW = base + OFF_WHLO + n0 * 1024;
    const uint32_t WxHiW = base + OFF_WXHI + n0 * 128;
    const uint32_t WxLoW = base + OFF_WXLO + n0 * 128;
    float* scr = reinterpret_cast<float*>(bptr + OFF_A0);   // epi scratch aliases A0

    const int em = tid & 63, eg = tid >> 6;  // epilogue mapping over 256 threads
    float bia[16];
#pragma unroll
    for (int q = 0; q < 16; q++) bia[q] = s_bias[eg * 16 + q];

    const int u0 = nc * 16 + eg * 4;
    const int kcb = u0 >> 7, ucol = u0 & 127;
    const unsigned hoff = (unsigned)em * 256u + ((((unsigned)ucol >> 3) ^ (em & 7)) << 4) + (ucol & 7) * 2u;
    unsigned* mycnt = &g_cnt[grp][nc >> 3][0];

    float cs[4] = {0.f, 0.f, 0.f, 0.f};
    int pf0 = 0, pf1 = 0, pfx = 0;

#pragma unroll 1
    for (int t = 0; t < Tt; t++) {
        const int wb = (t & 1) ^ 1;

        float acc[4][4];
#pragma unroll
        for (int a = 0; a < 4; a++)
#pragma unroll
            for (int bq = 0; bq < 4; bq++) acc[a][bq] = 0.f;

        // chunk 0 (A0)
        MBAR_WAIT(f0, pf0); pf0 ^= 1;
        compute_chunk<256, 1024, 8, 16384>(Abuf[0], WhHiW, WhLoW, 0, acc, lane, m0);
        if (lane == 0) MBARRIER_ARRIVE(e0);
        // chunk 1 (A1)
        MBAR_WAIT(f1, pf1); pf1 ^= 1;
        compute_chunk<256, 1024, 8, 16384>(Abuf[1], WhHiW, WhLoW, 16, acc, lane, m0);
        if (lane == 0) MBARRIER_ARRIVE(e1);
        // chunk 2 (A0) — empty arrival deferred to post-epilogue (scratch aliases A0)
        MBAR_WAIT(f0, pf0); pf0 ^= 1;
        compute_chunk<256, 1024, 8, 16384>(Abuf[0], WhHiW, WhLoW, 32, acc, lane, m0);
        // chunk 3 (A1)
        MBAR_WAIT(f1, pf1); pf1 ^= 1;
        compute_chunk<256, 1024, 8, 16384>(Abuf[1], WhHiW, WhLoW, 48, acc, lane, m0);
        if (lane == 0) MBARRIER_ARRIVE(e1);
        // x chunk
        MBAR_WAIT(fx, pfx); pfx ^= 1;
        compute_chunk<128, 128, 4, 8192>(XB, WxHiW, WxLoW, 0, acc, lane, m0);
        if (lane == 0) MBARRIER_ARRIVE(ex);

        // ---- epilogue ----
        BAR_COMPUTE();     // all warps done reading A0 (chunk 2) before scratch overwrite
        {
            const int r0 = m0 + (lane >> 2), cb = n0 + (lane & 3) * 2;
#pragma unroll
            for (int ti = 0; ti < 4; ti++) {
                *reinterpret_cast<float2*>(&scr[r0 * 68 + ti * 8 + cb])       = make_float2(acc[ti][0], acc[ti][1]);
                *reinterpret_cast<float2*>(&scr[(r0 + 8) * 68 + ti * 8 + cb]) = make_float2(acc[ti][2], acc[ti][3]);
            }
        }
        BAR_COMPUTE();
        {
            __align__(8) __nv_bfloat16 hh[4], hl[4];
            float hv4[4];
#pragma unroll
            for (int q = 0; q < 4; q++) {
                float4 v = *reinterpret_cast<float4*>(&scr[em * 68 + eg * 16 + q * 4]);
                float iv = sigm(v.x + bia[q * 4 + 0]);
                float fv = sigm(v.y + bia[q * 4 + 1]);
                float gv = tanh_(v.z + bia[q * 4 + 2]);
                float ov = sigm(v.w + bia[q * 4 + 3]);
                cs[q] = fv * cs[q] + iv * gv;
                float hv = ov * tanh_(cs[q]);
                hv4[q] = hv;
                hh[q] = __float2bfloat16(hv);
                hl[q] = __float2bfloat16(hv - __bfloat162float(hh[q]));
            }
            unsigned char* dst = &g_hblk[wb][grp][kcb][0] + hoff;
            *reinterpret_cast<uint2*>(dst)         = *reinterpret_cast<uint2*>(hh);
            *reinterpret_cast<uint2*>(dst + 16384) = *reinterpret_cast<uint2*>(hl);
            if (t == Tt - 1)
                *reinterpret_cast<float4*>(&g_hfinal[grp * 64 + em][u0]) =
                    make_float4(hv4[0], hv4[1], hv4[2], hv4[3]);
        }
        BAR_COMPUTE();     // all h writes + all scratch reads done
        if (tid == 0 && t < Tt - 1)
            asm volatile("red.release.gpu.global.add.u32 [%0], %1;" :: "l"(mycnt), "r"(1u) : "memory");
        if (lane == 0) MBARRIER_ARRIVE(e0);   // A0 free for next step's chunk 0
    }
}

// ---------------- final FC ----------------
__global__ void fc_kernel(const float* __restrict__ W_fc,
                          const float* __restrict__ b_fc,
                          float* __restrict__ out) {
    int b = threadIdx.x;
    float s = 0.f;
#pragma unroll 8
    for (int k = 0; k < Hh; k++) s += g_hfinal[b][k] * W_fc[k];
    out[b] = s + b_fc[0];
}

extern "C" void kernel_launch(void* const* d_in, const int* in_sizes, int n_in,
                              void* d_out, int out_size) {
    const float* x    = (const float*)d_in[0];
    const float* W_ih = (const float*)d_in[1];
    const float* W_hh = (const float*)d_in[2];
    const float* b_ih = (const float*)d_in[3];
    const float* b_hh = (const float*)d_in[4];
    const float* W_fc = (const float*)d_in[5];
    const float* b_fc = (const float*)d_in[6];
    float* out = (float*)d_out;

    cudaFuncSetAttribute(lstm_kernel, cudaFuncAttributeMaxDynamicSharedMemorySize, DSM_BYTES);

    init_kernel<<<1024, 256>>>(x);
    lstm_kernel<<<128, NTHR, DSM_BYTES>>>(W_ih, W_hh, b_ih, b_hh);
    fc_kernel<<<1, Bb>>>(W_fc, b_fc, out);
}

// round 8
// speedup vs baseline: 4.6953x; 1.1476x over previous
#include <cuda_runtime.h>
#include <cuda_fp16.h>
#include <cstdint>

// ---------------- problem constants ----------------
#define Bb   256
#define Tt   512
#define Ii   64
#define Hh   512
#define NTHR 288     // 8 compute warps (M4 x N2, warp tile M16 x N32) + 1 DMA warp

// SMEM layout offsets (from 1024-aligned base)
#define OFF_WHHI 0            // W_hh slice hi (fp16): [64 c][1024 B]
#define OFF_WHLO 65536        // W_hh slice lo (fp16)
#define OFF_WXHI 131072       // W_ih slice hi: [64 c][128 B]
#define OFF_WXLO 139264
#define OFF_A0   147456       // h chunk buf 0: 16KB (fp16, no lo plane)
#define OFF_A1   163840       // contiguous with A0 (epilogue scratch spans both)
#define OFF_XB   180224       // x buf: 8KB
#define DSM_BYTES (188416 + 1024)

// ---------------- persistent device state ----------------
// h tile layout: [buf][group][kchunk][16KB]; group = half*2 + mtile (64 batch rows)
// chunk = 64 rows x 128 units fp16 (256B/row), 16B-chunk swizzle
__device__ __align__(1024) unsigned char g_hblk[2][4][4][16384];
// x tile layout: [t][group][8KB] = 64 rows x 64 fp16 (128B/row), swizzled
__device__ __align__(1024) unsigned char g_xblk[Tt][4][8192];
__device__ float    g_hfinal[Bb][Hh];
__device__ unsigned g_cnt[4][4][16];   // [group][kchunk], padded to 64B

// ---------------- PTX helpers ----------------
__device__ __forceinline__ uint32_t smem_u32(const void* p) {
    uint32_t a;
    asm("{ .reg .u64 t; cvta.to.shared.u64 t, %1; cvt.u32.u64 %0, t; }" : "=r"(a) : "l"(p));
    return a;
}
#define MBARRIER_INIT(sa, cnt) \
    asm volatile("mbarrier.init.shared.b64 [%0], %1;" :: "r"((uint32_t)(sa)), "r"((uint32_t)(cnt)) : "memory")
#define MBARRIER_ARRIVE(sa) \
    asm volatile("mbarrier.arrive.shared.b64 _, [%0];" :: "r"((uint32_t)(sa)) : "memory")
#define MBAR_WAIT(sa, ph) do { \
    asm volatile("{\n\t.reg .pred P1;\n\tWL%=:\n\t" \
        "mbarrier.try_wait.parity.acquire.cta.shared::cta.b64 P1, [%0], %1, 0x989680;\n\t" \
        "@P1 bra.uni WD%=;\n\tbra.uni WL%=;\n\tWD%=:\n\t}" \
        :: "r"((uint32_t)(sa)), "r"((uint32_t)(ph)) : "memory"); \
} while (0)
#define FENCE_PROXY_ASYNC() asm volatile("fence.proxy.async;" ::: "memory")

__device__ __forceinline__ void tma_issue(uint32_t dst, const void* src, uint32_t bytes, uint32_t mbar) {
    asm volatile("mbarrier.arrive.expect_tx.shared.b64 _, [%0], %1;"
                 :: "r"(mbar), "r"(bytes) : "memory");
    asm volatile("cp.async.bulk.shared::cta.global.mbarrier::complete_tx::bytes [%0], [%1], %2, [%3];"
                 :: "r"(dst), "l"(src), "r"(bytes), "r"(mbar) : "memory");
}
__device__ __forceinline__ void ldsm4(uint32_t& a, uint32_t& b, uint32_t& c, uint32_t& d, uint32_t addr) {
    asm volatile("ldmatrix.sync.aligned.m8n8.x4.shared.b16 {%0,%1,%2,%3}, [%4];"
                 : "=r"(a), "=r"(b), "=r"(c), "=r"(d) : "r"(addr));
}
__device__ __forceinline__ void mma16816(float* c, uint32_t a0, uint32_t a1, uint32_t a2, uint32_t a3,
                                         uint32_t b0, uint32_t b1) {
    asm volatile("mma.sync.aligned.m16n8k16.row.col.f32.f16.f16.f32 "
                 "{%0,%1,%2,%3}, {%4,%5,%6,%7}, {%8,%9}, {%0,%1,%2,%3};"
                 : "+f"(c[0]), "+f"(c[1]), "+f"(c[2]), "+f"(c[3])
                 : "r"(a0), "r"(a1), "r"(a2), "r"(a3), "r"(b0), "r"(b1));
}
#define BAR_COMPUTE() asm volatile("bar.sync 1, 256;" ::: "memory")

// ---------------- activations ----------------
__device__ __forceinline__ float sigm(float x) { return __fdividef(1.f, 1.f + __expf(-x)); }
__device__ __forceinline__ float tanh_(float x) {
    x = fminf(fmaxf(x, -15.f), 15.f);
    float e = __expf(2.f * x);
    return __fdividef(e - 1.f, e + 1.f);
}

// ---------------- chunk GEMM: 2-term fp16-split via mma.sync ----------------
// A tile [64 rows x (NK*16) k] fp16 at Abase, rows RS bytes, 16B-chunk swizzle.
// W (hi+lo) rows WR bytes, base offset to this warp's N=32 slab.
template<int RS, int WR, int NK>
__device__ __forceinline__ void compute_chunk(uint32_t Abase, uint32_t Whi, uint32_t Wlo,
                                              int kw0, float (&acc)[4][4], int lane, int m0) {
    const int rA = m0 + (lane & 15);
    const int kA = lane >> 4;
    const int xr = lane & 7;
    const int cB = (lane & 7) + ((lane & 16) >> 1);
    const int kB = (lane >> 3) & 1;
    const uint32_t dlo = Wlo - Whi;
#pragma unroll
    for (int s = 0; s < NK; s++) {
        const int kcA = s * 2;
        uint32_t aaddr = Abase + rA * RS + (((kcA + kA) ^ xr) << 4);
        uint32_t ah[4];
        ldsm4(ah[0], ah[1], ah[2], ah[3], aaddr);
        const int kcW = kw0 + s * 2;
        uint32_t b01 = Whi + cB * WR + (((kcW + kB) ^ xr) << 4);
        uint32_t bh[8], bl[8];
        ldsm4(bh[0], bh[1], bh[2], bh[3], b01);
        ldsm4(bh[4], bh[5], bh[6], bh[7], b01 + 16 * WR);
        ldsm4(bl[0], bl[1], bl[2], bl[3], b01 + dlo);
        ldsm4(bl[4], bl[5], bl[6], bl[7], b01 + dlo + 16 * WR);
#pragma unroll
        for (int ti = 0; ti < 4; ti++) {
            mma16816(acc[ti], ah[0], ah[1], ah[2], ah[3], bh[2 * ti], bh[2 * ti + 1]);
            mma16816(acc[ti], ah[0], ah[1], ah[2], ah[3], bl[2 * ti], bl[2 * ti + 1]);
        }
    }
}

// ---------------- init: zero h buf0, reset counters, x -> fp16 tile layout ----------------
__global__ void init_kernel(const float* __restrict__ x) {
    int idx = blockIdx.x * blockDim.x + threadIdx.x;
    int stride = gridDim.x * blockDim.x;
    uint32_t* hz = reinterpret_cast<uint32_t*>(&g_hblk[0][0][0][0]);
    for (int i = idx; i < 4 * 4 * 16384 / 4; i += stride) hz[i] = 0u;
    for (int i = idx; i < Bb * Tt * Ii; i += stride) {
        int ii = i & 63;
        int t  = (i >> 6) & 511;
        int b  = i >> 15;
        int grp = b >> 6, m = b & 63;
        unsigned off = (unsigned)m * 128u + ((((unsigned)ii >> 3) ^ (m & 7)) << 4) + (ii & 7) * 2u;
        *reinterpret_cast<__half*>(&g_xblk[t][grp][off]) = __float2half(x[i]);
    }
    if (idx < 16) g_cnt[idx >> 2][idx & 3][0] = 0u;
}

// ---------------- persistent LSTM: warp-specialized, fp16 2-term ----------------
__global__ void __launch_bounds__(NTHR, 1) lstm_kernel(
    const float* __restrict__ W_ih,   // [2048, 64]
    const float* __restrict__ W_hh,   // [2048, 512]
    const float* __restrict__ b_ih,
    const float* __restrict__ b_hh)
{
    extern __shared__ char dsm[];
    // mbarriers: 0=f0 1=f1 2=fx 3=e0 4=e1 5=ex
    __shared__ __align__(8) unsigned long long s_mbar[6];
    __shared__ float s_bias[64];

    const int tid  = threadIdx.x;
    const int lane = tid & 31;
    const int wid  = tid >> 5;
    const int grp  = blockIdx.x >> 5;       // owns 64 batch rows
    const int nc   = blockIdx.x & 31;       // gate cols [nc*64, nc*64+64) -> 16 units

    uint32_t raw = smem_u32(dsm);
    uint32_t base = (raw + 1023u) & ~1023u;
    char* bptr = dsm + (base - raw);

    // ---- stage W slices (once), fp16 split hi/lo, swizzled ----
    for (int idx = tid; idx < 64 * Hh; idx += NTHR) {
        int c = idx >> 9, k = idx & 511;
        int row = (c & 3) * Hh + nc * 16 + (c >> 2);
        float w = W_hh[(size_t)row * Hh + k];
        __half hi = __float2half(w);
        __half lo = __float2half(w - __half2float(hi));
        unsigned off = (unsigned)c * 1024u + ((((unsigned)k >> 3) ^ (c & 7)) << 4) + (k & 7) * 2u;
        *reinterpret_cast<__half*>(bptr + OFF_WHHI + off) = hi;
        *reinterpret_cast<__half*>(bptr + OFF_WHLO + off) = lo;
    }
    for (int idx = tid; idx < 64 * Ii; idx += NTHR) {
        int c = idx >> 6, k = idx & 63;
        int row = (c & 3) * Hh + nc * 16 + (c >> 2);
        float w = W_ih[(size_t)row * Ii + k];
        __half hi = __float2half(w);
        __half lo = __float2half(w - __half2float(hi));
        unsigned off = (unsigned)c * 128u + ((((unsigned)k >> 3) ^ (c & 7)) << 4) + (k & 7) * 2u;
        *reinterpret_cast<__half*>(bptr + OFF_WXHI + off) = hi;
        *reinterpret_cast<__half*>(bptr + OFF_WXLO + off) = lo;
    }
    if (tid < 64) {
        int row = (tid & 3) * Hh + nc * 16 + (tid >> 2);
        s_bias[tid] = b_ih[row] + b_hh[row];
    }
    if (tid == 0) {
        MBARRIER_INIT(smem_u32(&s_mbar[0]), 1);   // full A0 (expect_tx)
        MBARRIER_INIT(smem_u32(&s_mbar[1]), 1);   // full A1
        MBARRIER_INIT(smem_u32(&s_mbar[2]), 1);   // full X
        MBARRIER_INIT(smem_u32(&s_mbar[3]), 8);   // empty A0 (8 compute warps)
        MBARRIER_INIT(smem_u32(&s_mbar[4]), 8);   // empty A1
        MBARRIER_INIT(smem_u32(&s_mbar[5]), 8);   // empty X
    }
    __syncthreads();

    const uint32_t f0 = smem_u32(&s_mbar[0]), f1 = smem_u32(&s_mbar[1]), fx = smem_u32(&s_mbar[2]);
    const uint32_t e0 = smem_u32(&s_mbar[3]), e1 = smem_u32(&s_mbar[4]), ex = smem_u32(&s_mbar[5]);
    const uint32_t Abuf[2] = { base + OFF_A0, base + OFF_A1 };
    const uint32_t XB = base + OFF_XB;

    // =========================== DMA warp ===========================
    if (wid == 8) {
        if (lane == 0) {
            volatile unsigned* cnt[4] = { &g_cnt[grp][0][0], &g_cnt[grp][1][0],
                                          &g_cnt[grp][2][0], &g_cnt[grp][3][0] };
            int pe0 = 1, pe1 = 1, pex = 1;
#pragma unroll 1
            for (int t = 0; t < Tt; t++) {
                const unsigned char (*hsrc)[16384] = g_hblk[t & 1][grp];
                const unsigned target = (unsigned)t * 8u;
                // x tile (no producer dependency)
                MBAR_WAIT(ex, pex); pex ^= 1;
                FENCE_PROXY_ASYNC();
                tma_issue(XB, &g_xblk[t][grp][0], 8192, fx);
                // h chunks 0..3, ring A0/A1
#pragma unroll
                for (int kc = 0; kc < 4; kc++) {
                    if (kc & 1) { MBAR_WAIT(e1, pe1); pe1 ^= 1; }
                    else        { MBAR_WAIT(e0, pe0); pe0 ^= 1; }
                    unsigned v;
                    while (true) {
                        asm volatile("ld.acquire.gpu.global.u32 %0, [%1];" : "=r"(v) : "l"(cnt[kc]));
                        if (v >= target) break;
                        asm volatile("nanosleep.u32 32;");
                    }
                    FENCE_PROXY_ASYNC();
                    tma_issue(Abuf[kc & 1], &hsrc[kc][0], 16384, (kc & 1) ? f1 : f0);
                }
            }
        }
        return;
    }

    // =========================== compute warps ===========================
    const int m0 = (wid >> 1) * 16;          // warp M offset within 64 rows
    const int n0 = (wid & 1) * 32;           // warp N offset within 64 cols
    const uint32_t WhHiW = base + OFF_WHHI + n0 * 1024;
    const uint32_t WhLoW = base + OFF_WHLO + n0 * 1024;
    const uint32_t WxHiW = base + OFF_WXHI + n0 * 128;
    const uint32_t WxLoW = base + OFF_WXLO + n0 * 128;
    float* scr = reinterpret_cast<float*>(bptr + OFF_A0);   // epi scratch spans A0+A1 (32KB)

    const int em = tid & 63, eg = tid >> 6;  // epilogue mapping over 256 threads
    float bia[16];
#pragma unroll
    for (int q = 0; q < 16; q++) bia[q] = s_bias[eg * 16 + q];

    const int u0 = nc * 16 + eg * 4;
    const int kcb = u0 >> 7, ucol = u0 & 127;
    const unsigned hoff = (unsigned)em * 256u + ((((unsigned)ucol >> 3) ^ (em & 7)) << 4) + (ucol & 7) * 2u;
    unsigned* mycnt = &g_cnt[grp][nc >> 3][0];

    float cs[4] = {0.f, 0.f, 0.f, 0.f};
    int pf0 = 0, pf1 = 0, pfx = 0;

#pragma unroll 1
    for (int t = 0; t < Tt; t++) {
        const int wb = (t & 1) ^ 1;

        float acc[4][4];
#pragma unroll
        for (int a = 0; a < 4; a++)
#pragma unroll
            for (int bq = 0; bq < 4; bq++) acc[a][bq] = 0.f;

        // chunk 0 (A0)
        MBAR_WAIT(f0, pf0); pf0 ^= 1;
        compute_chunk<256, 1024, 8>(Abuf[0], WhHiW, WhLoW, 0, acc, lane, m0);
        if (lane == 0) MBARRIER_ARRIVE(e0);
        // chunk 1 (A1)
        MBAR_WAIT(f1, pf1); pf1 ^= 1;
        compute_chunk<256, 1024, 8>(Abuf[1], WhHiW, WhLoW, 16, acc, lane, m0);
        if (lane == 0) MBARRIER_ARRIVE(e1);
        // chunk 2 (A0) — empty arrival deferred to post-epilogue (scratch aliases A0)
        MBAR_WAIT(f0, pf0); pf0 ^= 1;
        compute_chunk<256, 1024, 8>(Abuf[0], WhHiW, WhLoW, 32, acc, lane, m0);
        // chunk 3 (A1) — empty arrival deferred (scratch spans A1 too)
        MBAR_WAIT(f1, pf1); pf1 ^= 1;
        compute_chunk<256, 1024, 8>(Abuf[1], WhHiW, WhLoW, 48, acc, lane, m0);
        // x chunk
        MBAR_WAIT(fx, pfx); pfx ^= 1;
        compute_chunk<128, 128, 4>(XB, WxHiW, WxLoW, 0, acc, lane, m0);
        if (lane == 0) MBARRIER_ARRIVE(ex);

        // ---- epilogue ----
        BAR_COMPUTE();     // all warps done reading A0/A1 before scratch overwrite
        {
            const int r0 = m0 + (lane >> 2), cb = n0 + (lane & 3) * 2;
#pragma unroll
            for (int ti = 0; ti < 4; ti++) {
                *reinterpret_cast<float2*>(&scr[r0 * 68 + ti * 8 + cb])       = make_float2(acc[ti][0], acc[ti][1]);
                *reinterpret_cast<float2*>(&scr[(r0 + 8) * 68 + ti * 8 + cb]) = make_float2(acc[ti][2], acc[ti][3]);
            }
        }
        BAR_COMPUTE();
        {
            __align__(8) __half hh[4];
            float hv4[4];
#pragma unroll
            for (int q = 0; q < 4; q++) {
                float4 v = *reinterpret_cast<float4*>(&scr[em * 68 + eg * 16 + q * 4]);
                float iv = sigm(v.x + bia[q * 4 + 0]);
                float fv = sigm(v.y + bia[q * 4 + 1]);
                float gv = tanh_(v.z + bia[q * 4 + 2]);
                float ov = sigm(v.w + bia[q * 4 + 3]);
                cs[q] = fv * cs[q] + iv * gv;
                float hv = ov * tanh_(cs[q]);
                hv4[q] = hv;
                hh[q] = __float2half(hv);
            }
            unsigned char* dst = &g_hblk[wb][grp][kcb][0] + hoff;
            *reinterpret_cast<uint2*>(dst) = *reinterpret_cast<uint2*>(hh);
            if (t == Tt - 1)
                *reinterpret_cast<float4*>(&g_hfinal[grp * 64 + em][u0]) =
                    make_float4(hv4[0], hv4[1], hv4[2], hv4[3]);
        }
        BAR_COMPUTE();     // all h writes + all scratch reads done
        if (tid == 0 && t < Tt - 1)
            asm volatile("red.release.gpu.global.add.u32 [%0], %1;" :: "l"(mycnt), "r"(1u) : "memory");
        if (lane == 0) { MBARRIER_ARRIVE(e0); MBARRIER_ARRIVE(e1); }  // A0/A1 free
    }
}

// ---------------- final FC ----------------
__global__ void fc_kernel(const float* __restrict__ W_fc,
                          const float* __restrict__ b_fc,
                          float* __restrict__ out) {
    int b = threadIdx.x;
    float s = 0.f;
#pragma unroll 8
    for (int k = 0; k < Hh; k++) s += g_hfinal[b][k] * W_fc[k];
    out[b] = s + b_fc[0];
}

extern "C" void kernel_launch(void* const* d_in, const int* in_sizes, int n_in,
                              void* d_out, int out_size) {
    const float* x    = (const float*)d_in[0];
    const float* W_ih = (const float*)d_in[1];
    const float* W_hh = (const float*)d_in[2];
    const float* b_ih = (const float*)d_in[3];
    const float* b_hh = (const float*)d_in[4];
    const float* W_fc = (const float*)d_in[5];
    const float* b_fc = (const float*)d_in[6];
    float* out = (float*)d_out;

    cudaFuncSetAttribute(lstm_kernel, cudaFuncAttributeMaxDynamicSharedMemorySize, DSM_BYTES);

    init_kernel<<<1024, 256>>>(x);
    lstm_kernel<<<128, NTHR, DSM_BYTES>>>(W_ih, W_hh, b_ih, b_hh);
    fc_kernel<<<1, Bb>>>(W_fc, b_fc, out);
}